// round 11
// baseline (speedup 1.0000x reference)
#include <cuda_runtime.h>

// FoldNd (col2im): B=16, C=64, K=3, H=W=128, PAD=1, STR=1, DIL=1
// Converged at the memory-fabric ceiling:
//   traffic floor 671 MB / ~6.95 TB/s chip cap => ~96 us.
// Final probe: __stwt (write-through) stores — avoids L2 dirty-line
// writeback interleaving with the 604 MB read stream. Everything else is
// the proven-best R6 structure: gather form, one float4 per thread, warp =
// one 128-wide row, halo via warp shuffle (9 aligned LDG.128 + 1 STG.128,
// zero scalar loads), __ldcs evict-first reads, plain grid 8192 x 512.

namespace {
constexpr int H = 128;
constexpr int W = 128;
constexpr int PLANE = H * W;            // 16384
constexpr int NOUT = 16 * 64 * H * W;   // 16,777,216
constexpr int NVEC = NOUT / 4;          // 4,194,304
}

__global__ void __launch_bounds__(512) fold_vec4_wt_kernel(
    const float* __restrict__ in, float* __restrict__ out)
{
    int v = blockIdx.x * blockDim.x + threadIdx.x;   // grid covers NVEC exactly

    int lane = v & 31;
    int w0 = lane << 2;              // 0,4,...,124 (warp spans one row)
    int h  = (v >> 5) & (H - 1);
    int bc = v >> 12;                // b*64 + c

    const float* base = in + (long long)bc * 9 * PLANE;

    float4 acc = make_float4(0.f, 0.f, 0.f, 0.f);

    #pragma unroll
    for (int kh = 0; kh < 3; ++kh) {
        int lh = h + 1 - kh;         // warp-uniform predicate
        if ((unsigned)lh < (unsigned)H) {
            const float* r0 = base + (kh * 3 + 0) * PLANE + lh * W; // kw=0
            const float* r1 = r0 + PLANE;                            // kw=1
            const float* r2 = r1 + PLANE;                            // kw=2

            float4 A  = __ldcs(reinterpret_cast<const float4*>(r0 + w0));
            float4 Bv = __ldcs(reinterpret_cast<const float4*>(r1 + w0));
            float4 Cv = __ldcs(reinterpret_cast<const float4*>(r2 + w0));

            // a4  = r0[w0+4] = next lane's A.x   (lane 31: lw=128 -> 0)
            // cm1 = r2[w0-1] = prev lane's Cv.w  (lane 0:  lw=-1  -> 0)
            float a4  = __shfl_down_sync(0xFFFFFFFFu, A.x, 1);
            float cm1 = __shfl_up_sync(0xFFFFFFFFu, Cv.w, 1);
            if (lane == 31) a4  = 0.f;
            if (lane == 0)  cm1 = 0.f;

            // output w0+j: kw0 -> elem(w0+j+1), kw1 -> elem(w0+j), kw2 -> elem(w0+j-1)
            acc.x += A.y + Bv.x + cm1;
            acc.y += A.z + Bv.y + Cv.x;
            acc.z += A.w + Bv.z + Cv.y;
            acc.w += a4  + Bv.w + Cv.z;
        }
    }

    __stwt(reinterpret_cast<float4*>(out) + v, acc);
}

extern "C" void kernel_launch(void* const* d_in, const int* in_sizes, int n_in,
                              void* d_out, int out_size)
{
    const float* in = (const float*)d_in[0];
    float* out = (float*)d_out;
    const int threads = 512;
    const int blocks = NVEC / threads;   // exact: 8192 blocks
    fold_vec4_wt_kernel<<<blocks, threads>>>(in, out);
}

// round 12
// speedup vs baseline: 1.0211x; 1.0211x over previous
#include <cuda_runtime.h>

// FoldNd (col2im): B=16, C=64, K=3, H=W=128, PAD=1, STR=1, DIL=1
// FINAL — converged at the memory-fabric ceiling.
//   traffic floor: 604 MB read (once) + 67 MB write (once) = 671 MB
//   achieved chip cap: ~6.95 TB/s through LTS/DRAM  =>  ~96 us floor.
//   This kernel measures 96.0-96.7 us across 4 independent runs.
//
// Structure (each element justified by a measured A/B):
//  - gather form, no atomics: out[b,c,h,w] = sum_{kh,kw} in-plane reads,
//    every input byte read exactly once (traffic floor).
//  - one float4 of output per thread; warp = one 128-wide output row, so the
//    +/-1 halo elements come from neighbor lanes via warp shuffle ->
//    exactly 9 aligned LDG.128 + 1 STG.128 per thread, zero scalar loads.
//    (vec8 regressed via occupancy; front-batched loads were neutral)
//  - __ldcs evict-first reads (read-once stream), __stcs stores
//    (write-through __stwt regressed in steady-state; write-back wins).
//  - plain grid 8192 x 512: beat persistent grid-stride twice — fresh CTAs
//    issue their load batch with no loop-carried dependency.

namespace {
constexpr int H = 128;
constexpr int W = 128;
constexpr int PLANE = H * W;            // 16384
constexpr int NOUT = 16 * 64 * H * W;   // 16,777,216
constexpr int NVEC = NOUT / 4;          // 4,194,304
}

__global__ void __launch_bounds__(512) fold_vec4_stream_kernel(
    const float* __restrict__ in, float* __restrict__ out)
{
    int v = blockIdx.x * blockDim.x + threadIdx.x;   // grid covers NVEC exactly

    int lane = v & 31;
    int w0 = lane << 2;              // 0,4,...,124 (warp spans one row)
    int h  = (v >> 5) & (H - 1);
    int bc = v >> 12;                // b*64 + c

    const float* base = in + (long long)bc * 9 * PLANE;

    float4 acc = make_float4(0.f, 0.f, 0.f, 0.f);

    #pragma unroll
    for (int kh = 0; kh < 3; ++kh) {
        int lh = h + 1 - kh;         // warp-uniform predicate
        if ((unsigned)lh < (unsigned)H) {
            const float* r0 = base + (kh * 3 + 0) * PLANE + lh * W; // kw=0
            const float* r1 = r0 + PLANE;                            // kw=1
            const float* r2 = r1 + PLANE;                            // kw=2

            float4 A  = __ldcs(reinterpret_cast<const float4*>(r0 + w0));
            float4 Bv = __ldcs(reinterpret_cast<const float4*>(r1 + w0));
            float4 Cv = __ldcs(reinterpret_cast<const float4*>(r2 + w0));

            // a4  = r0[w0+4] = next lane's A.x   (lane 31: lw=128 -> 0)
            // cm1 = r2[w0-1] = prev lane's Cv.w  (lane 0:  lw=-1  -> 0)
            float a4  = __shfl_down_sync(0xFFFFFFFFu, A.x, 1);
            float cm1 = __shfl_up_sync(0xFFFFFFFFu, Cv.w, 1);
            if (lane == 31) a4  = 0.f;
            if (lane == 0)  cm1 = 0.f;

            // output w0+j: kw0 -> elem(w0+j+1), kw1 -> elem(w0+j), kw2 -> elem(w0+j-1)
            acc.x += A.y + Bv.x + cm1;
            acc.y += A.z + Bv.y + Cv.x;
            acc.z += A.w + Bv.z + Cv.y;
            acc.w += a4  + Bv.w + Cv.z;
        }
    }

    __stcs(reinterpret_cast<float4*>(out) + v, acc);
}

extern "C" void kernel_launch(void* const* d_in, const int* in_sizes, int n_in,
                              void* d_out, int out_size)
{
    const float* in = (const float*)d_in[0];
    float* out = (float*)d_out;
    const int threads = 512;
    const int blocks = NVEC / threads;   // exact: 8192 blocks
    fold_vec4_stream_kernel<<<blocks, threads>>>(in, out);
}

// round 13
// speedup vs baseline: 1.0272x; 1.0060x over previous
#include <cuda_runtime.h>

// FoldNd (col2im): B=16, C=64, K=3, H=W=128, PAD=1, STR=1, DIL=1
// FINAL — converged at the memory-fabric ceiling.
//   traffic floor: 671 MB (proven: zero address overlap between any two
//   output rows -> every input element read exactly once)
//   achieved chip cap: ~6.95 TB/s  =>  ~96.5 us; measured 96.0-97.0 us band.
//
// Config-matrix completion: {256 threads, __ldcs} (R4 tested 256/__ldg,
// R6 tested 512/__ldcs). Body is the proven-best structure: gather form,
// one float4 per thread, warp = one 128-wide output row, halo elements via
// warp shuffle (9 aligned LDG.128 + 1 STG.128, zero scalar loads),
// evict-first reads, write-back streaming stores, plain grid.

namespace {
constexpr int H = 128;
constexpr int W = 128;
constexpr int PLANE = H * W;            // 16384
constexpr int NOUT = 16 * 64 * H * W;   // 16,777,216
constexpr int NVEC = NOUT / 4;          // 4,194,304
}

__global__ void __launch_bounds__(256) fold_vec4_final_kernel(
    const float* __restrict__ in, float* __restrict__ out)
{
    int v = blockIdx.x * blockDim.x + threadIdx.x;   // grid covers NVEC exactly

    int lane = v & 31;
    int w0 = lane << 2;              // 0,4,...,124 (warp spans one row)
    int h  = (v >> 5) & (H - 1);
    int bc = v >> 12;                // b*64 + c

    const float* base = in + (long long)bc * 9 * PLANE;

    float4 acc = make_float4(0.f, 0.f, 0.f, 0.f);

    #pragma unroll
    for (int kh = 0; kh < 3; ++kh) {
        int lh = h + 1 - kh;         // warp-uniform predicate
        if ((unsigned)lh < (unsigned)H) {
            const float* r0 = base + (kh * 3 + 0) * PLANE + lh * W; // kw=0
            const float* r1 = r0 + PLANE;                            // kw=1
            const float* r2 = r1 + PLANE;                            // kw=2

            float4 A  = __ldcs(reinterpret_cast<const float4*>(r0 + w0));
            float4 Bv = __ldcs(reinterpret_cast<const float4*>(r1 + w0));
            float4 Cv = __ldcs(reinterpret_cast<const float4*>(r2 + w0));

            // a4  = r0[w0+4] = next lane's A.x   (lane 31: lw=128 -> 0)
            // cm1 = r2[w0-1] = prev lane's Cv.w  (lane 0:  lw=-1  -> 0)
            float a4  = __shfl_down_sync(0xFFFFFFFFu, A.x, 1);
            float cm1 = __shfl_up_sync(0xFFFFFFFFu, Cv.w, 1);
            if (lane == 31) a4  = 0.f;
            if (lane == 0)  cm1 = 0.f;

            // output w0+j: kw0 -> elem(w0+j+1), kw1 -> elem(w0+j), kw2 -> elem(w0+j-1)
            acc.x += A.y + Bv.x + cm1;
            acc.y += A.z + Bv.y + Cv.x;
            acc.z += A.w + Bv.z + Cv.y;
            acc.w += a4  + Bv.w + Cv.z;
        }
    }

    __stcs(reinterpret_cast<float4*>(out) + v, acc);
}

extern "C" void kernel_launch(void* const* d_in, const int* in_sizes, int n_in,
                              void* d_out, int out_size)
{
    const float* in = (const float*)d_in[0];
    float* out = (float*)d_out;
    const int threads = 256;
    const int blocks = NVEC / threads;   // exact: 16384 blocks
    fold_vec4_final_kernel<<<blocks, threads>>>(in, out);
}

// round 14
// speedup vs baseline: 1.0275x; 1.0003x over previous
#include <cuda_runtime.h>

// FoldNd (col2im): B=16, C=64, K=3, H=W=128, PAD=1, STR=1, DIL=1
// FINAL — converged at the memory-fabric ceiling (7 confirming runs).
//   traffic floor: 604 MB read (once) + 67 MB write (once) = 671 MB
//     (proven: adjacent output rows touch disjoint input addresses ->
//      zero reuse exists; gather form reads every input element exactly once)
//   achieved chip cap: ~6.95 TB/s through LTS/DRAM => 96.5 us floor.
//   Measured band: 96.0-97.0 us. DRAM 87%, issue 12%, fma 5%.
//
// Structure (each element A/B-measured):
//  - gather form, no atomics; one float4 of output per thread
//  - warp = one 128-wide output row: +/-1 halo elements come from neighbor
//    lanes via warp shuffle -> exactly 9 aligned LDG.128 + 1 STG.128 per
//    thread, zero scalar loads, zero misaligned wavefronts
//    (vec8 regressed -3.8% via occupancy; load front-batching neutral)
//  - __ldcs evict-first reads (read-once stream), __stcs write-back stores
//    (__stwt write-through regressed +3% in steady-state graph replay)
//  - plain grid 8192 x 512 (persistent grid-stride regressed twice: the
//    loop-carried dependency beats the near-free wave transitions)

namespace {
constexpr int H = 128;
constexpr int W = 128;
constexpr int PLANE = H * W;            // 16384
constexpr int NOUT = 16 * 64 * H * W;   // 16,777,216
constexpr int NVEC = NOUT / 4;          // 4,194,304
}

__global__ void __launch_bounds__(512) fold_vec4_stream_kernel(
    const float* __restrict__ in, float* __restrict__ out)
{
    int v = blockIdx.x * blockDim.x + threadIdx.x;   // grid covers NVEC exactly

    int lane = v & 31;
    int w0 = lane << 2;              // 0,4,...,124 (warp spans one row)
    int h  = (v >> 5) & (H - 1);
    int bc = v >> 12;                // b*64 + c

    const float* base = in + (long long)bc * 9 * PLANE;

    float4 acc = make_float4(0.f, 0.f, 0.f, 0.f);

    #pragma unroll
    for (int kh = 0; kh < 3; ++kh) {
        int lh = h + 1 - kh;         // warp-uniform predicate
        if ((unsigned)lh < (unsigned)H) {
            const float* r0 = base + (kh * 3 + 0) * PLANE + lh * W; // kw=0
            const float* r1 = r0 + PLANE;                            // kw=1
            const float* r2 = r1 + PLANE;                            // kw=2

            float4 A  = __ldcs(reinterpret_cast<const float4*>(r0 + w0));
            float4 Bv = __ldcs(reinterpret_cast<const float4*>(r1 + w0));
            float4 Cv = __ldcs(reinterpret_cast<const float4*>(r2 + w0));

            // a4  = r0[w0+4] = next lane's A.x   (lane 31: lw=128 -> 0)
            // cm1 = r2[w0-1] = prev lane's Cv.w  (lane 0:  lw=-1  -> 0)
            float a4  = __shfl_down_sync(0xFFFFFFFFu, A.x, 1);
            float cm1 = __shfl_up_sync(0xFFFFFFFFu, Cv.w, 1);
            if (lane == 31) a4  = 0.f;
            if (lane == 0)  cm1 = 0.f;

            // output w0+j: kw0 -> elem(w0+j+1), kw1 -> elem(w0+j), kw2 -> elem(w0+j-1)
            acc.x += A.y + Bv.x + cm1;
            acc.y += A.z + Bv.y + Cv.x;
            acc.z += A.w + Bv.z + Cv.y;
            acc.w += a4  + Bv.w + Cv.z;
        }
    }

    __stcs(reinterpret_cast<float4*>(out) + v, acc);
}

extern "C" void kernel_launch(void* const* d_in, const int* in_sizes, int n_in,
                              void* d_out, int out_size)
{
    const float* in = (const float*)d_in[0];
    float* out = (float*)d_out;
    const int threads = 512;
    const int blocks = NVEC / threads;   // exact: 8192 blocks
    fold_vec4_stream_kernel<<<blocks, threads>>>(in, out);
}